// round 11
// baseline (speedup 1.0000x reference)
#include <cuda_runtime.h>
#include <cuda_fp16.h>
#include <cstdint>

#define NNODES 100000
#define NEDGES 1600000
#define F_IN   256
#define HID    128
#define NL     4
#define NCOLS  40
#define JKDIM  (HID * NL)   // 512

// ---------------- device scratch (allocation-free rule: __device__ globals) --------
__device__ __align__(16) __half g_t[(size_t)NNODES * HID];   // u = dis*(A@W) (25.6 MB)
__device__ __align__(16) __half g_h[(size_t)NNODES * JKDIM]; // JK concat, fp16 (102.4 MB)
__device__ __align__(16) __half g_wt[102400];                // transposed fp16 weights
__device__ int   g_cnt[NNODES];
__device__ int   g_cur[NNODES];
__device__ int   g_off[NNODES + 1];
__device__ float g_dis[NNODES];
__device__ int   g_col[NEDGES];
__device__ int   g_bsum[128];

// transposed-weight offsets inside g_wt ([n][k] layouts)
#define WT_IN   0            // [128][256]
#define WT_1    32768        // [128][128]
#define WT_2    49152
#define WT_3    65536
#define WT_OUT  81920        // [40][512]

#define SCAN_B 1024
#define NB_SCAN ((NNODES + SCAN_B - 1) / SCAN_B)     // 98

// smem row stride in uint32 (half2) units: 32 data + 4 pad; fragment loads
// hit banks 4g + tg + const -> all 32 banks, conflict-free.
#define AST 36

// ---------------- fp16 MMA helper ---------------------------------------------------
__device__ __forceinline__ void mma_f16(float4& c, const uint32_t a[4],
                                        uint32_t b0, uint32_t b1) {
    asm volatile(
        "mma.sync.aligned.m16n8k16.row.col.f32.f16.f16.f32 "
        "{%0,%1,%2,%3}, {%4,%5,%6,%7}, {%8,%9}, {%0,%1,%2,%3};"
        : "+f"(c.x), "+f"(c.y), "+f"(c.z), "+f"(c.w)
        : "r"(a[0]), "r"(a[1]), "r"(a[2]), "r"(a[3]), "r"(b0), "r"(b1));
}

// ---------------- weight prep (transpose + fp16) + counter zeroing ------------------
__global__ void k_prep_w(const float* __restrict__ W_in, const float* __restrict__ W1,
                         const float* __restrict__ W2, const float* __restrict__ W3,
                         const float* __restrict__ W_out) {
    int i = blockIdx.x * blockDim.x + threadIdx.x;
    if (i < NNODES) { g_cnt[i] = 0; g_cur[i] = 0; }
    if (i < 32768) {                       // W_in [256][128] -> [128][256]
        int k = i >> 7, n = i & 127;
        g_wt[WT_IN + n * F_IN + k] = __float2half(W_in[i]);
    } else if (i < 32768 + 3 * 16384) {    // W1..W3 [128][128] -> [128][128]
        int j = i - 32768;
        int w = j >> 14, r = j & 16383;
        int k = r >> 7, n = r & 127;
        const float* W = (w == 0) ? W1 : (w == 1) ? W2 : W3;
        g_wt[WT_1 + w * 16384 + n * HID + k] = __float2half(W[r]);
    } else if (i < 102400) {               // W_out [512][40] -> [40][512]
        int j = i - 81920;
        int k = j / NCOLS, n = j % NCOLS;
        g_wt[WT_OUT + n * JKDIM + k] = __float2half(W_out[j]);
    }
}

// ---------------- CSR construction ------------------------------------------------
__global__ void k_count(const int* __restrict__ dst) {
    int e = blockIdx.x * blockDim.x + threadIdx.x;
    if (e < NEDGES) atomicAdd(&g_cnt[dst[e]], 1);
}

__global__ void k_scan1() {
    __shared__ int s[SCAN_B];
    int tid = threadIdx.x;
    int idx = blockIdx.x * SCAN_B + tid;
    int v = (idx < NNODES) ? g_cnt[idx] : 0;
    if (idx < NNODES) g_dis[idx] = rsqrtf((float)(v + 1));   // +1 self loop
    s[tid] = v;
    __syncthreads();
    #pragma unroll
    for (int o = 1; o < SCAN_B; o <<= 1) {
        int t = (tid >= o) ? s[tid - o] : 0;
        __syncthreads();
        s[tid] += t;
        __syncthreads();
    }
    if (idx < NNODES) g_off[idx] = s[tid] - v;
    if (tid == SCAN_B - 1) g_bsum[blockIdx.x] = s[tid];
}

__global__ void k_scan2() {
    __shared__ int s[128];
    int tid = threadIdx.x;
    if (tid < NB_SCAN) s[tid] = g_bsum[tid];
    __syncthreads();
    if (tid == 0) {
        int a = 0;
        for (int i = 0; i < NB_SCAN; i++) { int t = s[i]; s[i] = a; a += t; }
    }
    __syncthreads();
    if (tid < NB_SCAN) g_bsum[tid] = s[tid];
}

__global__ void k_scan3() {
    int idx = blockIdx.x * SCAN_B + threadIdx.x;
    if (idx < NNODES) g_off[idx] += g_bsum[blockIdx.x];
    if (idx == 0) g_off[NNODES] = NEDGES;
}

__global__ void k_fill(const int* __restrict__ src, const int* __restrict__ dst) {
    int e = blockIdx.x * blockDim.x + threadIdx.x;
    if (e < NEDGES) {
        int d = dst[e];
        int pos = g_off[d] + atomicAdd(&g_cur[d], 1);
        g_col[pos] = src[e];
    }
}

// ---------------- fp16 GEMM: [N x K] @ Wt -> g_t (fp16, scaled by dis[row]) --------
// BM=128, full BN=128; BK=64 (static smem, synchronous staging — proven R8 path).
// 8 warps (4 m x 2 n); warp tile 32x64.
template <int K, int FROM_H>
__global__ void __launch_bounds__(256) k_gemm_h(const float* __restrict__ A,
                                                int src_off, int wt_off) {
    __shared__ uint32_t Ah[128][AST];
    __shared__ uint32_t Ws[128][AST];

    int tid = threadIdx.x;
    int lane = tid & 31, wid = tid >> 5;
    int warp_m = wid & 3, warp_n = wid >> 2;
    int row0 = blockIdx.x * 128;
    int g = lane >> 2, tg = lane & 3;

    const __half* Wt = g_wt + wt_off;

    float4 c[2][8];
    #pragma unroll
    for (int mt = 0; mt < 2; mt++)
        #pragma unroll
        for (int nt = 0; nt < 8; nt++)
            c[mt][nt] = make_float4(0.f, 0.f, 0.f, 0.f);

    for (int kc = 0; kc < K; kc += 64) {
        #pragma unroll
        for (int j = 0; j < 4; j++) {
            int idx = tid + j * 256;
            int r = idx >> 3, q = idx & 7;
            int gr = row0 + r;
            if (FROM_H) {
                uint4 v = make_uint4(0, 0, 0, 0);
                if (gr < NNODES)
                    v = *(const uint4*)(g_h + (size_t)gr * JKDIM + src_off + kc + q * 8);
                *(uint4*)&Ah[r][q * 4] = v;
            } else {
                float4 v0 = make_float4(0.f, 0.f, 0.f, 0.f), v1 = v0;
                if (gr < NNODES) {
                    v0 = *(const float4*)(A + (size_t)gr * K + kc + q * 8);
                    v1 = *(const float4*)(A + (size_t)gr * K + kc + q * 8 + 4);
                }
                __half2 h0 = __floats2half2_rn(v0.x, v0.y);
                __half2 h1 = __floats2half2_rn(v0.z, v0.w);
                __half2 h2 = __floats2half2_rn(v1.x, v1.y);
                __half2 h3 = __floats2half2_rn(v1.z, v1.w);
                uint4 u = make_uint4(*(uint32_t*)&h0, *(uint32_t*)&h1,
                                     *(uint32_t*)&h2, *(uint32_t*)&h3);
                *(uint4*)&Ah[r][q * 4] = u;
            }
        }
        #pragma unroll
        for (int j = 0; j < 4; j++) {
            int idx = tid + j * 256;
            int n = idx >> 3, q = idx & 7;
            uint4 v = *(const uint4*)(Wt + (size_t)n * K + kc + q * 8);
            *(uint4*)&Ws[n][q * 4] = v;
        }
        __syncthreads();

        #pragma unroll
        for (int s = 0; s < 4; s++) {
            int k2 = s * 8;
            uint32_t a[2][4];
            #pragma unroll
            for (int mt = 0; mt < 2; mt++) {
                int r = warp_m * 32 + mt * 16 + g;
                a[mt][0] = Ah[r][k2 + tg];
                a[mt][1] = Ah[r + 8][k2 + tg];
                a[mt][2] = Ah[r][k2 + tg + 4];
                a[mt][3] = Ah[r + 8][k2 + tg + 4];
            }
            #pragma unroll
            for (int nt = 0; nt < 8; nt++) {
                int n = warp_n * 64 + nt * 8 + g;
                uint32_t b0 = Ws[n][k2 + tg];
                uint32_t b1 = Ws[n][k2 + tg + 4];
                #pragma unroll
                for (int mt = 0; mt < 2; mt++)
                    mma_f16(c[mt][nt], a[mt], b0, b1);
            }
        }
        if (kc + 64 < K) __syncthreads();
    }

    #pragma unroll
    for (int mt = 0; mt < 2; mt++) {
        int r_lo = row0 + warp_m * 32 + mt * 16 + g;
        int r_hi = r_lo + 8;
        float dlo = (r_lo < NNODES) ? g_dis[r_lo] : 0.f;
        float dhi = (r_hi < NNODES) ? g_dis[r_hi] : 0.f;
        #pragma unroll
        for (int nt = 0; nt < 8; nt++) {
            int col = warp_n * 64 + nt * 8 + 2 * tg;
            if (r_lo < NNODES) {
                __half2 v = __floats2half2_rn(c[mt][nt].x * dlo, c[mt][nt].y * dlo);
                *(__half2*)(g_t + (size_t)r_lo * HID + col) = v;
            }
            if (r_hi < NNODES) {
                __half2 v = __floats2half2_rn(c[mt][nt].z * dhi, c[mt][nt].w * dhi);
                *(__half2*)(g_t + (size_t)r_hi * HID + col) = v;
            }
        }
    }
}

// ---------------- Aggregation: 2 edges per warp iteration (LDG.128) -----------------
// Lanes 0-15 fetch edge e, lanes 16-31 fetch edge e+1 (same node, warp-uniform
// bounds); partials combined with shfl_xor(16).
__global__ void k_agg(const float* __restrict__ bias, int dst_off) {
    int node = blockIdx.x * 8 + (threadIdx.x >> 5);
    if (node >= NNODES) return;
    int lane = threadIdx.x & 31;
    int half = lane >> 4, l16 = lane & 15;

    const uint4* t4 = (const uint4*)g_t;   // 16 uint4 per 128-half row

    float4 a0 = make_float4(0.f, 0.f, 0.f, 0.f);
    float4 a1 = make_float4(0.f, 0.f, 0.f, 0.f);
    auto addin = [&](uint4 raw) {
        float2 f0 = __half22float2(*(__half2*)&raw.x);
        float2 f1 = __half22float2(*(__half2*)&raw.y);
        float2 f2 = __half22float2(*(__half2*)&raw.z);
        float2 f3 = __half22float2(*(__half2*)&raw.w);
        a0.x += f0.x; a0.y += f0.y; a0.z += f1.x; a0.w += f1.y;
        a1.x += f2.x; a1.y += f2.y; a1.z += f3.x; a1.w += f3.y;
    };

    if (half == 0) addin(__ldg(&t4[(size_t)node * 16 + l16]));   // self loop

    int e = g_off[node], end = g_off[node + 1];

    for (; e + 7 < end; e += 8) {          // 8 edges per iter, 4 per half-warp
        int s[4];
        #pragma unroll
        for (int i = 0; i < 4; i++) s[i] = __ldg(&g_col[e + 2 * i + half]);
        uint4 r[4];
        #pragma unroll
        for (int i = 0; i < 4; i++) r[i] = __ldg(&t4[(size_t)s[i] * 16 + l16]);
        #pragma unroll
        for (int i = 0; i < 4; i++) addin(r[i]);
    }
    for (; e < end; e += 2) {
        if (e + half < end) {
            int s0 = __ldg(&g_col[e + half]);
            addin(__ldg(&t4[(size_t)s0 * 16 + l16]));
        }
    }

    a0.x += __shfl_xor_sync(0xffffffffu, a0.x, 16);
    a0.y += __shfl_xor_sync(0xffffffffu, a0.y, 16);
    a0.z += __shfl_xor_sync(0xffffffffu, a0.z, 16);
    a0.w += __shfl_xor_sync(0xffffffffu, a0.w, 16);
    a1.x += __shfl_xor_sync(0xffffffffu, a1.x, 16);
    a1.y += __shfl_xor_sync(0xffffffffu, a1.y, 16);
    a1.z += __shfl_xor_sync(0xffffffffu, a1.z, 16);
    a1.w += __shfl_xor_sync(0xffffffffu, a1.w, 16);

    if (half == 0) {
        float dnode = __ldg(&g_dis[node]);
        float4 b0 = __ldg((const float4*)bias + l16 * 2);
        float4 b1 = __ldg((const float4*)bias + l16 * 2 + 1);
        a0.x = fmaxf(fmaf(dnode, a0.x, b0.x), 0.f);
        a0.y = fmaxf(fmaf(dnode, a0.y, b0.y), 0.f);
        a0.z = fmaxf(fmaf(dnode, a0.z, b0.z), 0.f);
        a0.w = fmaxf(fmaf(dnode, a0.w, b0.w), 0.f);
        a1.x = fmaxf(fmaf(dnode, a1.x, b1.x), 0.f);
        a1.y = fmaxf(fmaf(dnode, a1.y, b1.y), 0.f);
        a1.z = fmaxf(fmaf(dnode, a1.z, b1.z), 0.f);
        a1.w = fmaxf(fmaf(dnode, a1.w, b1.w), 0.f);

        __half2 h0 = __floats2half2_rn(a0.x, a0.y);
        __half2 h1 = __floats2half2_rn(a0.z, a0.w);
        __half2 h2 = __floats2half2_rn(a1.x, a1.y);
        __half2 h3 = __floats2half2_rn(a1.z, a1.w);
        uint4 packed = make_uint4(*(uint32_t*)&h0, *(uint32_t*)&h1,
                                  *(uint32_t*)&h2, *(uint32_t*)&h3);
        *(uint4*)(g_h + (size_t)node * JKDIM + dst_off + l16 * 8) = packed;
    }
}

// ---------------- fp16 output GEMM: g_h[N x 512] @ Wt_out + b -> out (fp32) --------
// BM=128, BK=64; synchronous staging (proven R8 path), 8 chunks.
__global__ void __launch_bounds__(256) k_gemm_out_h(const float* __restrict__ b,
                                                    float* __restrict__ C) {
    constexpr int K = JKDIM;
    __shared__ uint32_t Ah[128][AST];
    __shared__ uint32_t Ws[40][AST];

    int tid = threadIdx.x;
    int lane = tid & 31, wid = tid >> 5;
    int row0 = blockIdx.x * 128;
    int g = lane >> 2, tg = lane & 3;
    int m0 = wid * 16;

    const __half* Wt = g_wt + WT_OUT;

    float4 c[5];
    #pragma unroll
    for (int nt = 0; nt < 5; nt++) c[nt] = make_float4(0.f, 0.f, 0.f, 0.f);

    #pragma unroll
    for (int chunk = 0; chunk < 8; chunk++) {
        int kc = chunk * 64;
        #pragma unroll
        for (int j = 0; j < 4; j++) {
            int idx = tid + j * 256;
            int r = idx >> 3, q = idx & 7;
            int gr = row0 + r;
            uint4 v = make_uint4(0, 0, 0, 0);
            if (gr < NNODES)
                v = *(const uint4*)(g_h + (size_t)gr * K + kc + q * 8);
            *(uint4*)&Ah[r][q * 4] = v;
        }
        for (int idx = tid; idx < 320; idx += 256) {
            int n = idx >> 3, q = idx & 7;
            uint4 v = *(const uint4*)(Wt + (size_t)n * K + kc + q * 8);
            *(uint4*)&Ws[n][q * 4] = v;
        }
        __syncthreads();

        #pragma unroll
        for (int s = 0; s < 4; s++) {
            int k2 = s * 8;
            uint32_t a[4];
            int r = m0 + g;
            a[0] = Ah[r][k2 + tg];
            a[1] = Ah[r + 8][k2 + tg];
            a[2] = Ah[r][k2 + tg + 4];
            a[3] = Ah[r + 8][k2 + tg + 4];
            #pragma unroll
            for (int nt = 0; nt < 5; nt++) {
                int n = nt * 8 + g;
                uint32_t b0 = Ws[n][k2 + tg];
                uint32_t b1 = Ws[n][k2 + tg + 4];
                mma_f16(c[nt], a, b0, b1);
            }
        }
        __syncthreads();
    }

    int r_lo = row0 + m0 + g;
    int r_hi = r_lo + 8;
    #pragma unroll
    for (int nt = 0; nt < 5; nt++) {
        int col = nt * 8 + 2 * tg;
        float b0 = __ldg(&b[col]), b1 = __ldg(&b[col + 1]);
        if (r_lo < NNODES) {
            float2 v = make_float2(c[nt].x + b0, c[nt].y + b1);
            *(float2*)(C + (size_t)r_lo * NCOLS + col) = v;
        }
        if (r_hi < NNODES) {
            float2 v = make_float2(c[nt].z + b0, c[nt].w + b1);
            *(float2*)(C + (size_t)r_hi * NCOLS + col) = v;
        }
    }
}

// ---------------- launch ----------------------------------------------------------
extern "C" void kernel_launch(void* const* d_in, const int* in_sizes, int n_in,
                              void* d_out, int out_size) {
    const float* x     = (const float*)d_in[0];
    const int*   ei    = (const int*)d_in[1];
    const float* W_in  = (const float*)d_in[2];
    const float* b_in  = (const float*)d_in[3];
    const float* W1    = (const float*)d_in[4];
    const float* b1    = (const float*)d_in[5];
    const float* W2    = (const float*)d_in[6];
    const float* b2    = (const float*)d_in[7];
    const float* W3    = (const float*)d_in[8];
    const float* b3    = (const float*)d_in[9];
    const float* W_out = (const float*)d_in[10];
    const float* b_out = (const float*)d_in[11];
    float* out = (float*)d_out;

    const int* src = ei;            // edge_index[0]
    const int* dst = ei + NEDGES;   // edge_index[1]

    const int gemm_grid = (NNODES + 127) / 128;
    const int agg_grid  = (NNODES + 7) / 8;

    k_prep_w<<<(102400 + 255) / 256, 256>>>(W_in, W1, W2, W3, W_out);  // also zeros cnt/cur
    k_count<<<(NEDGES + 255) / 256, 256>>>(dst);
    k_scan1<<<NB_SCAN, SCAN_B>>>();
    k_scan2<<<1, 128>>>();
    k_gemm_h<F_IN, 0><<<gemm_grid, 256>>>(x, 0, WT_IN);
    k_scan3<<<NB_SCAN, SCAN_B>>>();
    k_fill<<<(NEDGES + 255) / 256, 256>>>(src, dst);
    k_agg<<<agg_grid, 256>>>(b_in, 0 * HID);

    const int wt_offs[3] = {WT_1, WT_2, WT_3};
    const float* bs[3] = {b1, b2, b3};
    for (int l = 1; l < NL; l++) {
        k_gemm_h<HID, 1><<<gemm_grid, 256>>>(nullptr, (l - 1) * HID, wt_offs[l - 1]);
        k_agg<<<agg_grid, 256>>>(bs[l - 1], l * HID);
    }

    k_gemm_out_h<<<gemm_grid, 256>>>(b_out, out);
}